// round 15
// baseline (speedup 1.0000x reference)
#include <cuda_runtime.h>
#include <cuda_bf16.h>

#define N_NODES 50000
#define N_EDGES 800000
#define N_RELS  8
#define NSEG    (N_NODES * N_RELS)
#define SCAN_CHUNK 2048
#define NCHUNK  ((NSEG + SCAN_CHUNK - 1) / SCAN_CHUNK)   // 196

// Scratch (device globals; zero-initialized at module load, invariants
// restored by the kernels themselves each call — no zeroing launches)
__device__ float g_h[(size_t)N_NODES * 64];
__device__ int   g_cnt[NSEG];          // zero at entry of every call
__device__ int   g_off[NSEG + 1];      // CSR offsets + sentinel
__device__ int   g_cur[NSEG];
__device__ int   g_agg[NCHUNK];
__device__ int   g_pre[NCHUNK];
__device__ int   g_done;               // zero at entry (fill resets)
__device__ int   g_rel;                // zero at entry (fill resets)
__device__ int   g_srcs[N_EDGES];
// Pre-split weights, layout [seg][n][k] (n-major, k contiguous), bf16
__device__ __nv_bfloat16 g_B1h[9 * 64 * 64];
__device__ __nv_bfloat16 g_B1l[9 * 64 * 64];
__device__ __nv_bfloat16 g_B2h[9 * 32 * 64];
__device__ __nv_bfloat16 g_B2l[9 * 32 * 64];

// ===== launch 0: edge counting + weight transpose/split (partitioned) ======
__global__ void count_zw_k(const int* __restrict__ ei,
                           const int* __restrict__ et,
                           const float* __restrict__ root1,
                           const float* __restrict__ W1,
                           const float* __restrict__ root2,
                           const float* __restrict__ W2,
                           __nv_bfloat16* __restrict__ b1h,
                           __nv_bfloat16* __restrict__ b1l,
                           __nv_bfloat16* __restrict__ b2h,
                           __nv_bfloat16* __restrict__ b2l) {
    int i = blockIdx.x * blockDim.x + threadIdx.x;
    constexpr int T1 = 9 * 64 * 64;
    constexpr int T2 = 9 * 32 * 64;
    if (i < N_EDGES) {
        int dst = ei[N_EDGES + i];
        int r   = et[i];
        atomicAdd(&g_cnt[dst * N_RELS + r], 1);
        return;
    }
    int j = i - N_EDGES;
    if (j >= T1 + T2) return;
    float w;
    __nv_bfloat16* bh;
    __nv_bfloat16* bl;
    int o;
    if (j < T1) {
        int k = j & 63;
        int n = (j >> 6) & 63;
        int s = j / (64 * 64);
        w = (s == 0) ? root1[k * 64 + n] : W1[((size_t)(s - 1) * 64 + k) * 64 + n];
        bh = b1h; bl = b1l; o = j;
    } else {
        int m = j - T1;
        int k = m & 63;
        int n = (m >> 6) & 31;
        int s = m / (64 * 32);
        w = (s == 0) ? root2[k * 32 + n] : W2[((size_t)(s - 1) * 64 + k) * 32 + n];
        bh = b2h; bl = b2l; o = m;
    }
    __nv_bfloat16 h = __float2bfloat16(w);
    bh[o] = h;
    bl[o] = __float2bfloat16(w - __bfloat162float(h));
}

// ===== launch 1: single-pass scan, parallel last-block publish =============
__global__ void scan_k() {
    __shared__ int sh[256];
    __shared__ int flag;
    __shared__ int base_sh;
    int t = threadIdx.x, b = blockIdx.x;
    int base = b * SCAN_CHUNK + t * 8;
    int v[8]; int s = 0;
    #pragma unroll
    for (int i = 0; i < 8; i++) {
        int idx = base + i;
        v[i] = (idx < NSEG) ? g_cnt[idx] : 0;
        s += v[i];
    }
    sh[t] = s;
    __syncthreads();
    for (int off = 1; off < 256; off <<= 1) {
        int u = (t >= off) ? sh[t - off] : 0;
        __syncthreads();
        sh[t] += u;
        __syncthreads();
    }
    int total = sh[255];
    int run = sh[t] - s;   // exclusive prefix within chunk

    if (t == 0) {
        g_agg[b] = total;
        __threadfence();
        int old = atomicAdd(&g_done, 1);
        flag = (old == NCHUNK - 1);
    }
    __syncthreads();
    if (flag) {
        int a = (t < NCHUNK) ? g_agg[t] : 0;
        sh[t] = a;
        __syncthreads();
        for (int off = 1; off < 256; off <<= 1) {
            int u = (t >= off) ? sh[t - off] : 0;
            __syncthreads();
            sh[t] += u;
            __syncthreads();
        }
        if (t < NCHUNK) g_pre[t] = sh[t] - a;
        __threadfence();
        __syncthreads();
        if (t == 0) atomicExch(&g_rel, 1);
    }
    if (t == 0) {
        while (atomicAdd(&g_rel, 0) == 0) { }
        __threadfence();
        base_sh = g_pre[b];
        if (b == 0) g_off[NSEG] = N_EDGES;  // sentinel
    }
    __syncthreads();
    int bb = base_sh;
    #pragma unroll
    for (int i = 0; i < 8; i++) {
        int idx = base + i;
        if (idx < NSEG) {
            int o = bb + run;
            g_off[idx] = o;
            g_cur[idx] = o;
            g_cnt[idx] = 0;               // restore zero-at-entry invariant
        }
        run += v[i];
    }
}

// ===== launch 2: CSR fill + scan-state reset ===============================
__global__ void fill_k(const int* __restrict__ ei,
                       const int* __restrict__ et) {
    int e = blockIdx.x * blockDim.x + threadIdx.x;
    if (e == 0) { g_done = 0; g_rel = 0; }  // restore for next call
    if (e < N_EDGES) {
        int src = ei[e];
        int dst = ei[N_EDGES + e];
        int r   = et[e];
        int p = atomicAdd(&g_cur[dst * N_RELS + r], 1);
        g_srcs[p] = src;
    }
}

// ============================ mma helpers ==================================
__device__ __forceinline__ unsigned smem_u32(const void* p) {
    unsigned a;
    asm("{ .reg .u64 t; cvta.to.shared.u64 t, %1; cvt.u32.u64 %0, t; }"
        : "=r"(a) : "l"(p));
    return a;
}

__device__ __forceinline__ void ldsm4(unsigned& r0, unsigned& r1,
                                      unsigned& r2, unsigned& r3, unsigned a) {
    asm volatile("ldmatrix.sync.aligned.m8n8.x4.shared.b16 {%0,%1,%2,%3}, [%4];"
                 : "=r"(r0), "=r"(r1), "=r"(r2), "=r"(r3) : "r"(a));
}

__device__ __forceinline__ void mma_bf16(float* c, const unsigned* a,
                                         unsigned b0, unsigned b1) {
    asm volatile(
        "mma.sync.aligned.m16n8k16.row.col.f32.bf16.bf16.f32 "
        "{%0,%1,%2,%3}, {%4,%5,%6,%7}, {%8,%9}, {%0,%1,%2,%3};"
        : "+f"(c[0]), "+f"(c[1]), "+f"(c[2]), "+f"(c[3])
        : "r"(a[0]), "r"(a[1]), "r"(a[2]), "r"(a[3]), "r"(b0), "r"(b1));
}

__device__ __forceinline__ void cp_async16(unsigned dst, const void* src) {
    asm volatile("cp.async.cg.shared.global [%0], [%1], 16;"
                 :: "r"(dst), "l"(src) : "memory");
}
__device__ __forceinline__ void cp_commit() {
    asm volatile("cp.async.commit_group;" ::: "memory");
}
__device__ __forceinline__ void cp_wait0() {
    asm volatile("cp.async.wait_group 0;" ::: "memory");
}

// split 16 fp32 -> bf16 hi/lo (two uint4 each)
__device__ __forceinline__ void split16(const float* v, uint4* hp, uint4* lp) {
    unsigned h[8], l[8];
    #pragma unroll
    for (int j = 0; j < 8; j++) {
        float a = v[2 * j], b = v[2 * j + 1];
        __nv_bfloat16 ha = __float2bfloat16(a);
        __nv_bfloat16 hb = __float2bfloat16(b);
        __nv_bfloat162 hh; hh.x = ha; hh.y = hb;
        __nv_bfloat162 ll;
        ll.x = __float2bfloat16(a - __bfloat162float(ha));
        ll.y = __float2bfloat16(b - __bfloat162float(hb));
        h[j] = *reinterpret_cast<unsigned*>(&hh);
        l[j] = *reinterpret_cast<unsigned*>(&ll);
    }
    hp[0] = make_uint4(h[0], h[1], h[2], h[3]);
    hp[1] = make_uint4(h[4], h[5], h[6], h[7]);
    lp[0] = make_uint4(l[0], l[1], l[2], l[3]);
    lp[1] = make_uint4(l[4], l[5], l[6], l[7]);
}

// ============================ fused gather + mma GEMM ======================
// Tile: 128 rows x FOUT cols, 512 threads (16 warps as 8x2), occupancy 2
// (= 32 warps/SM, 50%). 9 segments of K=64; A built by CSR gather (split
// bf16), B via cp.async from preconverted globals. Double buffered.
#define ASTRB 144
template<int FOUT, bool RELU>
__global__ __launch_bounds__(512, 2)
void rgcn_mma_k(const float* __restrict__ X,
                const __nv_bfloat16* __restrict__ Bh,   // [9][FOUT][64]
                const __nv_bfloat16* __restrict__ Bl,
                const float* __restrict__ bias,
                float* __restrict__ out) {
    extern __shared__ char smem[];
    constexpr int APART = 128 * ASTRB;         // 18432 B
    constexpr int BPART = FOUT * ASTRB;
    constexpr int OFF_B = 4 * APART;

    const int tid = threadIdx.x;
    const int wid = tid >> 5;
    const int lane = tid & 31;
    const int row0 = blockIdx.x * 128;
    const unsigned sb = smem_u32(smem);

    // gather role: 4 threads per row, 16 floats each (512 thr = 128 rows)
    const int rrow = tid >> 2;
    const int q = tid & 3;
    const int grow = row0 + rrow;

    // CSR headers from offsets alone (cnt = diff, inv = rcp)
    int off9[9];
    float inv8[8];
    if (grow < N_NODES) {
        const int4* op = (const int4*)(g_off + grow * N_RELS);
        int4 o0 = op[0], o1 = op[1];
        off9[0]=o0.x; off9[1]=o0.y; off9[2]=o0.z; off9[3]=o0.w;
        off9[4]=o1.x; off9[5]=o1.y; off9[6]=o1.z; off9[7]=o1.w;
        off9[8] = g_off[grow * N_RELS + 8];
        #pragma unroll
        for (int r = 0; r < 8; r++) {
            int c = off9[r + 1] - off9[r];
            inv8[r] = __frcp_rn((float)(c > 1 ? c : 1));
        }
    } else {
        #pragma unroll
        for (int r = 0; r < 9; r++) off9[r] = 0;
        #pragma unroll
        for (int r = 0; r < 8; r++) inv8[r] = 0.f;
    }

    auto produce = [&](int s, int buf) {
        // ---- B: cp.async preconverted [FOUT][64] bf16 rows ----
        {
            unsigned Bhs = sb + OFF_B + (2 * buf + 0) * BPART;
            unsigned Bls = sb + OFF_B + (2 * buf + 1) * BPART;
            const uint4* sh = (const uint4*)(Bh + (size_t)s * FOUT * 64);
            const uint4* sl = (const uint4*)(Bl + (size_t)s * FOUT * 64);
            int lin = tid;                       // FOUT*8 uint4 per part
            if (lin < FOUT * 8) {
                int n = lin >> 3, c = lin & 7;
                unsigned d = n * ASTRB + c * 16;
                cp_async16(Bhs + d, sh + lin);
                cp_async16(Bls + d, sl + lin);
            }
            cp_commit();
        }

        // ---- A: gather (seg 0 = identity), split, store ----
        float v[16];
        if (s == 0) {
            if (grow < N_NODES) {
                const float4* xp = (const float4*)(X + (size_t)grow * 64) + q * 4;
                #pragma unroll
                for (int i = 0; i < 4; i++) {
                    float4 t = xp[i];
                    v[4*i] = t.x; v[4*i+1] = t.y; v[4*i+2] = t.z; v[4*i+3] = t.w;
                }
            } else {
                #pragma unroll
                for (int i = 0; i < 16; i++) v[i] = 0.f;
            }
        } else {
            #pragma unroll
            for (int i = 0; i < 16; i++) v[i] = 0.f;
            int rel = s - 1;
            int start = off9[rel];
            int cnt = off9[rel + 1] - start;
            float w = inv8[rel];
            int src_next = (cnt > 0) ? g_srcs[start] : 0;   // prefetch head
            for (int i = 0; i < cnt; i++) {
                int src = src_next;
                if (i + 1 < cnt) src_next = g_srcs[start + i + 1];
                const float4* xp = (const float4*)(X + (size_t)src * 64) + q * 4;
                #pragma unroll
                for (int j = 0; j < 4; j++) {
                    float4 t = xp[j];
                    v[4*j] += t.x; v[4*j+1] += t.y; v[4*j+2] += t.z; v[4*j+3] += t.w;
                }
            }
            #pragma unroll
            for (int i = 0; i < 16; i++) v[i] *= w;
        }
        uint4 hp[2], lp[2];
        split16(v, hp, lp);
        char* Ahi = smem + (2 * buf + 0) * APART;
        char* Alo = smem + (2 * buf + 1) * APART;
        unsigned o = rrow * ASTRB + q * 32;
        *(uint4*)(Ahi + o) = hp[0];
        *(uint4*)(Ahi + o + 16) = hp[1];
        *(uint4*)(Alo + o) = lp[0];
        *(uint4*)(Alo + o + 16) = lp[1];
    };

    // warp tile: 16 rows x (FOUT/2) cols; 16 warps as 8 rowGroups x 2 colGroups
    const int warpRow = wid & 7;
    const int warpCol = wid >> 3;
    constexpr int NT = FOUT / 16;        // n-tiles (8 cols each): 4 or 2
    float c[NT][4];
    #pragma unroll
    for (int t = 0; t < NT; t++)
        #pragma unroll
        for (int j = 0; j < 4; j++) c[t][j] = 0.f;

    const int lrow = (lane & 7) + ((lane >> 3) & 1) * 8;
    const unsigned lkoff = (lane >> 4) * 16;

    produce(0, 0);
    cp_wait0();
    __syncthreads();

    for (int seg = 0; seg < 9; seg++) {
        const int b = seg & 1;
        if (seg < 8) produce(seg + 1, b ^ 1);

        const unsigned Ahi = sb + (2 * b + 0) * APART;
        const unsigned Alo = sb + (2 * b + 1) * APART;
        const unsigned Bhi = sb + OFF_B + (2 * b + 0) * BPART;
        const unsigned Blo = sb + OFF_B + (2 * b + 1) * BPART;
        const unsigned aoff = (warpRow * 16 + lrow) * ASTRB + lkoff;

        #pragma unroll
        for (int kc = 0; kc < 4; kc++) {
            unsigned ah[4], al[4];
            ldsm4(ah[0], ah[1], ah[2], ah[3], Ahi + aoff + kc * 32);
            ldsm4(al[0], al[1], al[2], al[3], Alo + aoff + kc * 32);
            #pragma unroll
            for (int p = 0; p < NT / 2; p++) {
                unsigned boff = (warpCol * (FOUT / 2) + p * 16 + lrow) * ASTRB
                              + lkoff + kc * 32;
                unsigned bh0, bh1, bh2, bh3, bl0, bl1, bl2, bl3;
                ldsm4(bh0, bh1, bh2, bh3, Bhi + boff);
                ldsm4(bl0, bl1, bl2, bl3, Blo + boff);
                mma_bf16(c[2*p],     ah, bh0, bh2);
                mma_bf16(c[2*p],     ah, bl0, bl2);
                mma_bf16(c[2*p],     al, bh0, bh2);
                mma_bf16(c[2*p + 1], ah, bh1, bh3);
                mma_bf16(c[2*p + 1], ah, bl1, bl3);
                mma_bf16(c[2*p + 1], al, bh1, bh3);
            }
        }
        if (seg < 8) cp_wait0();
        __syncthreads();
    }

    // epilogue
    const int er = row0 + warpRow * 16 + (lane >> 2);
    #pragma unroll
    for (int t = 0; t < NT; t++) {
        int cc = warpCol * (FOUT / 2) + t * 8 + (lane & 3) * 2;
        float2 bv = *(const float2*)&bias[cc];
        if (er < N_NODES) {
            float2 o = make_float2(c[t][0] + bv.x, c[t][1] + bv.y);
            if (RELU) { o.x = fmaxf(o.x, 0.f); o.y = fmaxf(o.y, 0.f); }
            *(float2*)&out[(size_t)er * FOUT + cc] = o;
        }
        if (er + 8 < N_NODES) {
            float2 o = make_float2(c[t][2] + bv.x, c[t][3] + bv.y);
            if (RELU) { o.x = fmaxf(o.x, 0.f); o.y = fmaxf(o.y, 0.f); }
            *(float2*)&out[(size_t)(er + 8) * FOUT + cc] = o;
        }
    }
}

// ---------------------------------------------------------------------------
extern "C" void kernel_launch(void* const* d_in, const int* in_sizes, int n_in,
                              void* d_out, int out_size) {
    const float* x     = (const float*)d_in[0];
    const int*   ei    = (const int*)d_in[1];   // int32 on device (JAX x64 off)
    const int*   et    = (const int*)d_in[2];
    const float* W1    = (const float*)d_in[3];
    const float* root1 = (const float*)d_in[4];
    const float* b1    = (const float*)d_in[5];
    const float* W2    = (const float*)d_in[6];
    const float* root2 = (const float*)d_in[7];
    const float* b2    = (const float*)d_in[8];
    float* out = (float*)d_out;

    float* h_ptr = nullptr;
    cudaGetSymbolAddress((void**)&h_ptr, g_h);
    __nv_bfloat16 *b1h, *b1l, *b2h, *b2l;
    cudaGetSymbolAddress((void**)&b1h, g_B1h);
    cudaGetSymbolAddress((void**)&b1l, g_B1l);
    cudaGetSymbolAddress((void**)&b2h, g_B2h);
    cudaGetSymbolAddress((void**)&b2l, g_B2l);

    constexpr int SMEM1 = 4 * 128 * ASTRB + 4 * 64 * ASTRB;  // 110592
    constexpr int SMEM2 = 4 * 128 * ASTRB + 4 * 32 * ASTRB;  // 92160
    cudaFuncSetAttribute(rgcn_mma_k<64, true>,
                         cudaFuncAttributeMaxDynamicSharedMemorySize, SMEM1);
    cudaFuncSetAttribute(rgcn_mma_k<32, false>,
                         cudaFuncAttributeMaxDynamicSharedMemorySize, SMEM2);

    const int edgeBlocks = (N_EDGES + 255) / 256;
    const int mmaBlocks  = (N_NODES + 127) / 128;
    constexpr int WTOT = 9 * 64 * 64 + 9 * 32 * 64;
    const int czBlocks   = (N_EDGES + WTOT + 255) / 256;

    // 3-launch CSR build; mma1 stays at launch index 3 for ncu capture
    count_zw_k<<<czBlocks, 256>>>(ei, et, root1, W1, root2, W2,
                                  b1h, b1l, b2h, b2l);
    scan_k<<<NCHUNK, 256>>>();
    fill_k<<<edgeBlocks, 256>>>(ei, et);

    // Layer 1 (fused gather + split-bf16 mma.sync GEMM)
    rgcn_mma_k<64, true><<<mmaBlocks, 512, SMEM1>>>(x, b1h, b1l, b1, h_ptr);

    // Layer 2
    rgcn_mma_k<32, false><<<mmaBlocks, 512, SMEM2>>>(h_ptr, b2h, b2l, b2, out);
}

// round 16
// speedup vs baseline: 1.2220x; 1.2220x over previous
#include <cuda_runtime.h>
#include <cuda_bf16.h>

#define N_NODES 50000
#define N_EDGES 800000
#define N_RELS  8
#define NSEG    (N_NODES * N_RELS)
#define SCAN_CHUNK 2048
#define NCHUNK  ((NSEG + SCAN_CHUNK - 1) / SCAN_CHUNK)   // 196

// Fragment-linear B record counts: [seg][kc][ntile][lane]
#define R1 (9 * 4 * 8 * 32)    // layer1: FOUT=64 -> 8 n-tiles
#define R2 (9 * 4 * 4 * 32)    // layer2: FOUT=32 -> 4 n-tiles

// Scratch (device globals; zero-initialized at module load, invariants
// restored by the kernels themselves each call — no zeroing launches)
__device__ float g_h[(size_t)N_NODES * 64];
__device__ int   g_cnt[NSEG];          // zero at entry of every call
__device__ int   g_off[NSEG + 1];      // CSR offsets + sentinel
__device__ int   g_cur[NSEG];
__device__ int   g_agg[NCHUNK];
__device__ int   g_pre[NCHUNK];
__device__ int   g_done;               // zero at entry (fill resets)
__device__ int   g_rel;                // zero at entry (fill resets)
__device__ int   g_srcs[N_EDGES];
// B in MMA-fragment-linear layout: per (seg,kc,ntile,lane) 16B =
// [b0_hi, b1_hi, b0_lo, b1_lo]  (b0 = k-pair at k0, b1 = k-pair at k0+8)
__device__ uint4 g_Bf1[R1];
__device__ uint4 g_Bf2[R2];

// ===== launch 0: edge counting + weight -> fragment-linear split ===========
__device__ __forceinline__ unsigned pack_bf2(float a, float b) {
    __nv_bfloat162 h;
    h.x = __float2bfloat16(a);
    h.y = __float2bfloat16(b);
    return *reinterpret_cast<unsigned*>(&h);
}

__global__ void count_zw_k(const int* __restrict__ ei,
                           const int* __restrict__ et,
                           const float* __restrict__ root1,
                           const float* __restrict__ W1,
                           const float* __restrict__ root2,
                           const float* __restrict__ W2) {
    int i = blockIdx.x * blockDim.x + threadIdx.x;
    if (i < N_EDGES) {
        int dst = ei[N_EDGES + i];
        int r   = et[i];
        atomicAdd(&g_cnt[dst * N_RELS + r], 1);
        return;
    }
    int j = i - N_EDGES;
    if (j >= R1 + R2) return;

    int lane, nt, kc, s, F;
    const float* root;
    const float* W;
    uint4* dstp;
    if (j < R1) {
        lane = j & 31; nt = (j >> 5) & 7; kc = (j >> 8) & 3; s = j >> 10;
        F = 64; root = root1; W = W1; dstp = g_Bf1 + j;
    } else {
        int m = j - R1;
        lane = m & 31; nt = (m >> 5) & 3; kc = (m >> 7) & 3; s = m >> 9;
        F = 32; root = root2; W = W2; dstp = g_Bf2 + m;
    }
    int n  = nt * 8 + (lane >> 2);
    int k0 = kc * 16 + (lane & 3) * 2;

    float a0, a1, a2, a3;
    if (s == 0) {
        a0 = root[k0 * F + n];       a1 = root[(k0 + 1) * F + n];
        a2 = root[(k0 + 8) * F + n]; a3 = root[(k0 + 9) * F + n];
    } else {
        const float* Ws = W + (size_t)(s - 1) * 64 * F;
        a0 = Ws[k0 * F + n];         a1 = Ws[(k0 + 1) * F + n];
        a2 = Ws[(k0 + 8) * F + n];   a3 = Ws[(k0 + 9) * F + n];
    }
    float l0 = a0 - __bfloat162float(__float2bfloat16(a0));
    float l1 = a1 - __bfloat162float(__float2bfloat16(a1));
    float l2 = a2 - __bfloat162float(__float2bfloat16(a2));
    float l3 = a3 - __bfloat162float(__float2bfloat16(a3));
    uint4 o;
    o.x = pack_bf2(a0, a1);
    o.y = pack_bf2(a2, a3);
    o.z = pack_bf2(l0, l1);
    o.w = pack_bf2(l2, l3);
    *dstp = o;
}

// ===== launch 1: single-pass scan, parallel last-block publish =============
__global__ void scan_k() {
    __shared__ int sh[256];
    __shared__ int flag;
    __shared__ int base_sh;
    int t = threadIdx.x, b = blockIdx.x;
    int base = b * SCAN_CHUNK + t * 8;
    int v[8]; int s = 0;
    #pragma unroll
    for (int i = 0; i < 8; i++) {
        int idx = base + i;
        v[i] = (idx < NSEG) ? g_cnt[idx] : 0;
        s += v[i];
    }
    sh[t] = s;
    __syncthreads();
    for (int off = 1; off < 256; off <<= 1) {
        int u = (t >= off) ? sh[t - off] : 0;
        __syncthreads();
        sh[t] += u;
        __syncthreads();
    }
    int total = sh[255];
    int run = sh[t] - s;   // exclusive prefix within chunk

    if (t == 0) {
        g_agg[b] = total;
        __threadfence();
        int old = atomicAdd(&g_done, 1);
        flag = (old == NCHUNK - 1);
    }
    __syncthreads();
    if (flag) {
        int a = (t < NCHUNK) ? g_agg[t] : 0;
        sh[t] = a;
        __syncthreads();
        for (int off = 1; off < 256; off <<= 1) {
            int u = (t >= off) ? sh[t - off] : 0;
            __syncthreads();
            sh[t] += u;
            __syncthreads();
        }
        if (t < NCHUNK) g_pre[t] = sh[t] - a;
        __threadfence();
        __syncthreads();
        if (t == 0) atomicExch(&g_rel, 1);
    }
    if (t == 0) {
        while (atomicAdd(&g_rel, 0) == 0) { }
        __threadfence();
        base_sh = g_pre[b];
        if (b == 0) g_off[NSEG] = N_EDGES;  // sentinel
    }
    __syncthreads();
    int bb = base_sh;
    #pragma unroll
    for (int i = 0; i < 8; i++) {
        int idx = base + i;
        if (idx < NSEG) {
            int o = bb + run;
            g_off[idx] = o;
            g_cur[idx] = o;
            g_cnt[idx] = 0;               // restore zero-at-entry invariant
        }
        run += v[i];
    }
}

// ===== launch 2: CSR fill + scan-state reset ===============================
__global__ void fill_k(const int* __restrict__ ei,
                       const int* __restrict__ et) {
    int e = blockIdx.x * blockDim.x + threadIdx.x;
    if (e == 0) { g_done = 0; g_rel = 0; }  // restore for next call
    if (e < N_EDGES) {
        int src = ei[e];
        int dst = ei[N_EDGES + e];
        int r   = et[e];
        int p = atomicAdd(&g_cur[dst * N_RELS + r], 1);
        g_srcs[p] = src;
    }
}

// ============================ mma helpers ==================================
__device__ __forceinline__ unsigned smem_u32(const void* p) {
    unsigned a;
    asm("{ .reg .u64 t; cvta.to.shared.u64 t, %1; cvt.u32.u64 %0, t; }"
        : "=r"(a) : "l"(p));
    return a;
}

__device__ __forceinline__ void ldsm4(unsigned& r0, unsigned& r1,
                                      unsigned& r2, unsigned& r3, unsigned a) {
    asm volatile("ldmatrix.sync.aligned.m8n8.x4.shared.b16 {%0,%1,%2,%3}, [%4];"
                 : "=r"(r0), "=r"(r1), "=r"(r2), "=r"(r3) : "r"(a));
}

__device__ __forceinline__ void mma_bf16(float* c, const unsigned* a,
                                         unsigned b0, unsigned b1) {
    asm volatile(
        "mma.sync.aligned.m16n8k16.row.col.f32.bf16.bf16.f32 "
        "{%0,%1,%2,%3}, {%4,%5,%6,%7}, {%8,%9}, {%0,%1,%2,%3};"
        : "+f"(c[0]), "+f"(c[1]), "+f"(c[2]), "+f"(c[3])
        : "r"(a[0]), "r"(a[1]), "r"(a[2]), "r"(a[3]), "r"(b0), "r"(b1));
}

// split 16 fp32 -> bf16 hi/lo (two uint4 each)
__device__ __forceinline__ void split16(const float* v, uint4* hp, uint4* lp) {
    unsigned h[8], l[8];
    #pragma unroll
    for (int j = 0; j < 8; j++) {
        float a = v[2 * j], b = v[2 * j + 1];
        __nv_bfloat16 ha = __float2bfloat16(a);
        __nv_bfloat16 hb = __float2bfloat16(b);
        __nv_bfloat162 hh; hh.x = ha; hh.y = hb;
        __nv_bfloat162 ll;
        ll.x = __float2bfloat16(a - __bfloat162float(ha));
        ll.y = __float2bfloat16(b - __bfloat162float(hb));
        h[j] = *reinterpret_cast<unsigned*>(&hh);
        l[j] = *reinterpret_cast<unsigned*>(&ll);
    }
    hp[0] = make_uint4(h[0], h[1], h[2], h[3]);
    hp[1] = make_uint4(h[4], h[5], h[6], h[7]);
    lp[0] = make_uint4(l[0], l[1], l[2], l[3]);
    lp[1] = make_uint4(l[4], l[5], l[6], l[7]);
}

// ============================ fused gather + mma GEMM ======================
// Tile: 64 rows x FOUT cols, 256 threads (8 warps as 4x2), occ 3.
// A built by CSR gather (split bf16) in smem, double buffered.
// B comes STRAIGHT FROM GLOBAL in fragment-linear layout: one coalesced
// LDG.128 per (kc, n-tile) per warp -> no B smem, no cp.async, no B LDSM.
#define ASTRB 144
template<int FOUT, bool RELU>
__global__ __launch_bounds__(256, 3)
void rgcn_mma_k(const float* __restrict__ X,
                const uint4* __restrict__ Bf,   // [9][4][FOUT/8][32] uint4
                const float* __restrict__ bias,
                float* __restrict__ out) {
    extern __shared__ char smem[];
    constexpr int APART = 64 * ASTRB;          // 9216 B
    constexpr int NTG = FOUT / 8;              // global n-tiles per segment

    const int tid = threadIdx.x;
    const int wid = tid >> 5;
    const int lane = tid & 31;
    const int row0 = blockIdx.x * 64;
    const unsigned sb = smem_u32(smem);

    // gather role: 4 threads per row, 16 floats each
    const int rrow = tid >> 2;
    const int q = tid & 3;
    const int grow = row0 + rrow;

    // CSR headers from offsets alone (cnt = diff, inv = rcp)
    int off9[9];
    float inv8[8];
    if (grow < N_NODES) {
        const int4* op = (const int4*)(g_off + grow * N_RELS);
        int4 o0 = op[0], o1 = op[1];
        off9[0]=o0.x; off9[1]=o0.y; off9[2]=o0.z; off9[3]=o0.w;
        off9[4]=o1.x; off9[5]=o1.y; off9[6]=o1.z; off9[7]=o1.w;
        off9[8] = g_off[grow * N_RELS + 8];
        #pragma unroll
        for (int r = 0; r < 8; r++) {
            int c = off9[r + 1] - off9[r];
            inv8[r] = __frcp_rn((float)(c > 1 ? c : 1));
        }
    } else {
        #pragma unroll
        for (int r = 0; r < 9; r++) off9[r] = 0;
        #pragma unroll
        for (int r = 0; r < 8; r++) inv8[r] = 0.f;
    }

    auto produce = [&](int s, int buf) {
        float v[16];
        if (s == 0) {
            if (grow < N_NODES) {
                const float4* xp = (const float4*)(X + (size_t)grow * 64) + q * 4;
                #pragma unroll
                for (int i = 0; i < 4; i++) {
                    float4 t = xp[i];
                    v[4*i] = t.x; v[4*i+1] = t.y; v[4*i+2] = t.z; v[4*i+3] = t.w;
                }
            } else {
                #pragma unroll
                for (int i = 0; i < 16; i++) v[i] = 0.f;
            }
        } else {
            #pragma unroll
            for (int i = 0; i < 16; i++) v[i] = 0.f;
            int rel = s - 1;
            int start = off9[rel];
            int cnt = off9[rel + 1] - start;
            float w = inv8[rel];
            int src_next = (cnt > 0) ? g_srcs[start] : 0;   // prefetch head
            for (int i = 0; i < cnt; i++) {
                int src = src_next;
                if (i + 1 < cnt) src_next = g_srcs[start + i + 1];
                const float4* xp = (const float4*)(X + (size_t)src * 64) + q * 4;
                #pragma unroll
                for (int j = 0; j < 4; j++) {
                    float4 t = xp[j];
                    v[4*j] += t.x; v[4*j+1] += t.y; v[4*j+2] += t.z; v[4*j+3] += t.w;
                }
            }
            #pragma unroll
            for (int i = 0; i < 16; i++) v[i] *= w;
        }
        uint4 hp[2], lp[2];
        split16(v, hp, lp);
        char* Ahi = smem + (2 * buf + 0) * APART;
        char* Alo = smem + (2 * buf + 1) * APART;
        unsigned o = rrow * ASTRB + q * 32;
        *(uint4*)(Ahi + o) = hp[0];
        *(uint4*)(Ahi + o + 16) = hp[1];
        *(uint4*)(Alo + o) = lp[0];
        *(uint4*)(Alo + o + 16) = lp[1];
    };

    // warp tile: 16 rows x (FOUT/2) cols
    const int warpRow = wid & 3;
    const int warpCol = wid >> 2;
    constexpr int NT = FOUT / 16;        // n-tiles per warpCol... (4 or 2)
    float c[NT][4];
    #pragma unroll
    for (int t = 0; t < NT; t++)
        #pragma unroll
        for (int j = 0; j < 4; j++) c[t][j] = 0.f;

    const int lrow = (lane & 7) + ((lane >> 3) & 1) * 8;
    const unsigned lkoff = (lane >> 4) * 16;

    produce(0, 0);
    __syncthreads();

    for (int seg = 0; seg < 9; seg++) {
        const int b = seg & 1;
        if (seg < 8) produce(seg + 1, b ^ 1);

        const unsigned Ahi = sb + (2 * b + 0) * APART;
        const unsigned Alo = sb + (2 * b + 1) * APART;
        const unsigned aoff = (warpRow * 16 + lrow) * ASTRB + lkoff;

        #pragma unroll
        for (int kc = 0; kc < 4; kc++) {
            unsigned ah[4], al[4];
            ldsm4(ah[0], ah[1], ah[2], ah[3], Ahi + aoff + kc * 32);
            ldsm4(al[0], al[1], al[2], al[3], Alo + aoff + kc * 32);
            const uint4* bp = Bf + ((size_t)(seg * 4 + kc) * NTG
                                    + warpCol * NT) * 32 + lane;
            #pragma unroll
            for (int p = 0; p < NT / 2; p++) {
                uint4 f0 = bp[(p * 2 + 0) * 32];
                uint4 f1 = bp[(p * 2 + 1) * 32];
                mma_bf16(c[2*p],     ah, f0.x, f0.y);   // hi*hi
                mma_bf16(c[2*p],     ah, f0.z, f0.w);   // hi*lo
                mma_bf16(c[2*p],     al, f0.x, f0.y);   // lo*hi
                mma_bf16(c[2*p + 1], ah, f1.x, f1.y);
                mma_bf16(c[2*p + 1], ah, f1.z, f1.w);
                mma_bf16(c[2*p + 1], al, f1.x, f1.y);
            }
        }
        __syncthreads();
    }

    // epilogue
    const int er = row0 + warpRow * 16 + (lane >> 2);
    #pragma unroll
    for (int t = 0; t < NT; t++) {
        int cc = warpCol * (FOUT / 2) + t * 8 + (lane & 3) * 2;
        float2 bv = *(const float2*)&bias[cc];
        if (er < N_NODES) {
            float2 o = make_float2(c[t][0] + bv.x, c[t][1] + bv.y);
            if (RELU) { o.x = fmaxf(o.x, 0.f); o.y = fmaxf(o.y, 0.f); }
            *(float2*)&out[(size_t)er * FOUT + cc] = o;
        }
        if (er + 8 < N_NODES) {
            float2 o = make_float2(c[t][2] + bv.x, c[t][3] + bv.y);
            if (RELU) { o.x = fmaxf(o.x, 0.f); o.y = fmaxf(o.y, 0.f); }
            *(float2*)&out[(size_t)(er + 8) * FOUT + cc] = o;
        }
    }
}

// ---------------------------------------------------------------------------
extern "C" void kernel_launch(void* const* d_in, const int* in_sizes, int n_in,
                              void* d_out, int out_size) {
    const float* x     = (const float*)d_in[0];
    const int*   ei    = (const int*)d_in[1];   // int32 on device (JAX x64 off)
    const int*   et    = (const int*)d_in[2];
    const float* W1    = (const float*)d_in[3];
    const float* root1 = (const float*)d_in[4];
    const float* b1    = (const float*)d_in[5];
    const float* W2    = (const float*)d_in[6];
    const float* root2 = (const float*)d_in[7];
    const float* b2    = (const float*)d_in[8];
    float* out = (float*)d_out;

    float* h_ptr = nullptr;
    cudaGetSymbolAddress((void**)&h_ptr, g_h);
    uint4 *bf1, *bf2;
    cudaGetSymbolAddress((void**)&bf1, g_Bf1);
    cudaGetSymbolAddress((void**)&bf2, g_Bf2);

    constexpr int SMEM = 4 * 64 * ASTRB;   // 36864 (A hi/lo double-buffered)
    cudaFuncSetAttribute(rgcn_mma_k<64, true>,
                         cudaFuncAttributeMaxDynamicSharedMemorySize, SMEM);
    cudaFuncSetAttribute(rgcn_mma_k<32, false>,
                         cudaFuncAttributeMaxDynamicSharedMemorySize, SMEM);

    const int edgeBlocks = (N_EDGES + 255) / 256;
    const int mmaBlocks  = (N_NODES + 63) / 64;
    const int czBlocks   = (N_EDGES + R1 + R2 + 255) / 256;

    // 3-launch CSR build; mma1 stays at user-launch index 3 for ncu capture
    count_zw_k<<<czBlocks, 256>>>(ei, et, root1, W1, root2, W2);
    scan_k<<<NCHUNK, 256>>>();
    fill_k<<<edgeBlocks, 256>>>(ei, et);

    // Layer 1 (fused gather + split-bf16 mma.sync, B direct-from-global)
    rgcn_mma_k<64, true><<<mmaBlocks, 256, SMEM>>>(x, bf1, b1, h_ptr);

    // Layer 2
    rgcn_mma_k<32, false><<<mmaBlocks, 256, SMEM>>>(h_ptr, bf2, b2, out);
}